// round 15
// baseline (speedup 1.0000x reference)
#include <cuda_runtime.h>
#include <cuda_fp16.h>
#include <cstdint>

#define B 8
#define C 256
#define HW 4096
#define BN_EPS 1e-5f
#define SPLIT 8
#define CHUNK (HW / SPLIT)   // 512
#define NT 32
#define PLANE 16384          // 128 rows x 128 bytes
#define SW128(o) ((o) ^ (((o) >> 3) & 0x70))

// ---- device scratch ----
__device__ uint32_t g_Yhi[3][(size_t)B * C * HW / 2];   // fp16 hi plane
__device__ uint32_t g_Xsp[B][NT][4][4096];              // x hi plane, swizzled image
__device__ uint32_t g_Wsp[3][2][4][4096];               // W hi plane, swizzled image
__device__ float    g_a[3][C], g_d[3][C];
__device__ float    g_S[3][B * C];
__device__ float    g_Psum[3][(size_t)B * NT * C];
__device__ float    g_Psum2[3][(size_t)B * NT * C];
__device__ float    g_Gpart[SPLIT][(size_t)B * C * C];
__device__ uint32_t g_M2hi[(size_t)B * C * C / 2];
__device__ float    g_r[B * C];

// ---- helpers ----
__device__ __forceinline__ uint32_t smaddr(const void* p) {
    return (uint32_t)__cvta_generic_to_shared(p);
}
__device__ __forceinline__ void mma16816h(float* c, const uint32_t* a, const uint32_t* b) {
    asm volatile(
        "mma.sync.aligned.m16n8k16.row.col.f32.f16.f16.f32 "
        "{%0,%1,%2,%3}, {%4,%5,%6,%7}, {%8,%9}, {%0,%1,%2,%3};\n"
        : "+f"(c[0]), "+f"(c[1]), "+f"(c[2]), "+f"(c[3])
        : "r"(a[0]), "r"(a[1]), "r"(a[2]), "r"(a[3]), "r"(b[0]), "r"(b[1]));
}
__device__ __forceinline__ void ldfrag(uint32_t* r, uint32_t base, int row0, int kb, int lane) {
    int rl = row0 + (lane & 15);
    int cb = kb + ((lane >> 4) << 4);
    uint32_t a = base + (uint32_t)SW128(rl * 128 + cb);
    asm volatile("ldmatrix.sync.aligned.m8n8.x4.shared.b16 {%0,%1,%2,%3}, [%4];"
                 : "=r"(r[0]), "=r"(r[1]), "=r"(r[2]), "=r"(r[3]) : "r"(a));
}
// 1-term chunk: acc += Ah * Bh
__device__ __forceinline__ void mma_chunk1(
    float (*acc)[8][4], uint32_t Ah, uint32_t Bh, int lane, int wm, int wn)
{
#pragma unroll
    for (int ks = 0; ks < 4; ks++) {
        const int kb = ks * 32;
        uint32_t ah[2][4];
        ldfrag(ah[0], Ah, wm,      kb, lane);
        ldfrag(ah[1], Ah, wm + 16, kb, lane);
#pragma unroll
        for (int j = 0; j < 4; j++) {
            uint32_t bh[4];
            ldfrag(bh, Bh, wn + j * 16, kb, lane);
            uint32_t b0h[2] = {bh[0], bh[2]}, b1h[2] = {bh[1], bh[3]};
#pragma unroll
            for (int i = 0; i < 2; i++) {
                mma16816h(acc[i][2 * j],     ah[i], b0h);
                mma16816h(acc[i][2 * j + 1], ah[i], b1h);
            }
        }
    }
}
__device__ __forceinline__ void cp16(uint32_t dst, const void* src) {
    asm volatile("cp.async.cg.shared.global [%0], [%1], 16;"
                 :: "r"(dst), "l"((unsigned long long)__cvta_generic_to_global(src)) : "memory");
}
__device__ __forceinline__ void cp_commit() {
    asm volatile("cp.async.commit_group;" ::: "memory");
}
template <int N>
__device__ __forceinline__ void cp_wait() {
    asm volatile("cp.async.wait_group %0;" :: "n"(N) : "memory");
}

// ---------------------------------------------------------------------------
// K0: prep = wsplit (blocks 0..23) + xsplit (blocks 24..1047). 256 thr.
// ---------------------------------------------------------------------------
__global__ __launch_bounds__(256) void prep(
    const float* __restrict__ x,
    const float* __restrict__ Wq, const float* __restrict__ Wk,
    const float* __restrict__ Wv)
{
    const int tid = threadIdx.x;
    if (blockIdx.x < 24) {
        // W -> fp16 hi plane, swizzled
        const int p = blockIdx.x >> 3, rem = blockIdx.x & 7;
        const int mh = rem >> 2, kt = rem & 3;
        const float* W = (p == 0) ? Wq : (p == 1) ? Wk : Wv;
        const int m0 = mh * 128, k0 = kt * 64;
        char* dh = (char*)g_Wsp[p][mh][kt];
#pragma unroll
        for (int i = 0; i < 16; i++) {
            int idx = i * 256 + tid;
            int r = idx >> 5, k2 = idx & 31;
            float2 w2 = *(const float2*)&W[(size_t)(m0 + r) * C + k0 + 2 * k2];
            __half2 hp = __floats2half2_rn(w2.x, w2.y);
            *(uint32_t*)(dh + SW128(r * 128 + k2 * 4)) = *reinterpret_cast<uint32_t*>(&hp);
        }
        return;
    }
    // x -> fp16 hi plane, transposed + swizzled
    __shared__ float xs[64][129];
    const int id = blockIdx.x - 24;          // 0..1023: [b][kt][nt]
    const int nt = id & 31, kt = (id >> 5) & 3, b = id >> 7;
    const int n0 = nt * 128, c0 = kt * 64;
    const float* xb = x + (size_t)b * C * HW;

#pragma unroll
    for (int i = 0; i < 8; i++) {
        int idx = i * 256 + tid;
        int c = idx >> 5, f4 = idx & 31;
        float4 v = *(const float4*)&xb[(size_t)(c0 + c) * HW + n0 + f4 * 4];
        xs[c][f4 * 4 + 0] = v.x; xs[c][f4 * 4 + 1] = v.y;
        xs[c][f4 * 4 + 2] = v.z; xs[c][f4 * 4 + 3] = v.w;
    }
    __syncthreads();

    char* dh = (char*)g_Xsp[b][nt][kt];
#pragma unroll
    for (int i = 0; i < 16; i++) {
        int idx = i * 256 + tid;
        int n = idx >> 5, k2 = idx & 31;
        __half2 hp = __floats2half2_rn(xs[2 * k2][n], xs[2 * k2 + 1][n]);
        *(uint32_t*)(dh + SW128(n * 128 + k2 * 4)) = *reinterpret_cast<uint32_t*>(&hp);
    }
}

// ---------------------------------------------------------------------------
// K1: proj, 1-term.  grid (32, 2, 24), 256 thr, 64KB smem.
// ---------------------------------------------------------------------------
__global__ __launch_bounds__(256, 2) void proj_gemm(
    const float* __restrict__ bq, const float* __restrict__ bk,
    const float* __restrict__ bv)
{
    extern __shared__ char smraw[];
    uint32_t sa0 = smaddr(smraw);
    char* sm = smraw + ((1024u - (sa0 & 1023u)) & 1023u);
    const uint32_t sb = smaddr(sm);   // [buf][Ah,Bh][PLANE]

    const int p = blockIdx.z >> 3, b = blockIdx.z & 7;
    const float* bias = (p == 0) ? bq : (p == 1) ? bk : bv;
    const int tid = threadIdx.x, lane = tid & 31, wid = tid >> 5;
    const int nt = blockIdx.x, mh = blockIdx.y;
    const int n0 = nt * 128, m0 = mh * 128;
    const int wm = (wid & 3) * 32, wn = (wid >> 2) * 64;

    auto stage = [&](int kt, int t) {
        const uint32_t base = sb + t * 2 * PLANE;
        const uint32_t* Ah = g_Wsp[p][mh][kt];
        const uint32_t* Bh = g_Xsp[b][nt][kt];
#pragma unroll
        for (int i = 0; i < 4; i++) {
            int idx = i * 256 + tid;
            uint32_t doff = idx * 16;
            cp16(base + doff,         Ah + idx * 4);
            cp16(base + PLANE + doff, Bh + idx * 4);
        }
        cp_commit();
    };

    stage(0, 0);
    float acc[2][8][4] = {};
#pragma unroll
    for (int kt = 0; kt < 4; kt++) {
        if (kt < 3) { stage(kt + 1, (kt + 1) & 1); cp_wait<1>(); }
        else        { cp_wait<0>(); }
        __syncthreads();
        const uint32_t base = sb + (kt & 1) * 2 * PLANE;
        mma_chunk1(acc, base, base + PLANE, lane, wm, wn);
        __syncthreads();
    }

    // epilogue: +bias, hi stores, per-row partial stats
    const int g = lane >> 2, tg = lane & 3;
    float rsum[4] = {}, rsum2[4] = {};
#pragma unroll
    for (int i = 0; i < 2; i++)
#pragma unroll
        for (int j = 0; j < 8; j++) {
            int r0 = m0 + wm + i * 16 + g;
            int cc = n0 + wn + j * 8 + tg * 2;
            float bi = bias[r0];
            float y0 = acc[i][j][0] + bi, y1 = acc[i][j][1] + bi;
            rsum[i * 2]  += y0 + y1;
            rsum2[i * 2] += y0 * y0 + y1 * y1;
            __half2 hp = __floats2half2_rn(y0, y1);
            size_t off = ((size_t)(b * C + r0) * HW + cc) >> 1;
            g_Yhi[p][off] = *reinterpret_cast<uint32_t*>(&hp);
            int r1 = r0 + 8;
            bi = bias[r1];
            y0 = acc[i][j][2] + bi; y1 = acc[i][j][3] + bi;
            rsum[i * 2 + 1]  += y0 + y1;
            rsum2[i * 2 + 1] += y0 * y0 + y1 * y1;
            hp = __floats2half2_rn(y0, y1);
            off = ((size_t)(b * C + r1) * HW + cc) >> 1;
            g_Yhi[p][off] = *reinterpret_cast<uint32_t*>(&hp);
        }
#pragma unroll
    for (int q = 0; q < 4; q++) {
        rsum[q]  += __shfl_xor_sync(0xffffffffu, rsum[q], 1);
        rsum[q]  += __shfl_xor_sync(0xffffffffu, rsum[q], 2);
        rsum2[q] += __shfl_xor_sync(0xffffffffu, rsum2[q], 1);
        rsum2[q] += __shfl_xor_sync(0xffffffffu, rsum2[q], 2);
    }
    float* sbf  = (float*)sm;
    float* sbf2 = (float*)(sm + 2048);
    if (tg == 0) {
        const int half = wn >> 6;
#pragma unroll
        for (int q = 0; q < 4; q++) {
            int r = wm + (q >> 1) * 16 + (q & 1) * 8 + g;
            sbf[r * 2 + half]  = rsum[q];
            sbf2[r * 2 + half] = rsum2[q];
        }
    }
    __syncthreads();
    if (tid < 128) {
        size_t off = ((size_t)b * NT + nt) * C + m0 + tid;
        g_Psum[p][off]  = sbf[tid * 2] + sbf[tid * 2 + 1];
        g_Psum2[p][off] = sbf2[tid * 2] + sbf2[tid * 2 + 1];
    }
}

// ---------------------------------------------------------------------------
// K2: BN affine from partial stats. grid 3*C, 256.
// ---------------------------------------------------------------------------
__global__ __launch_bounds__(256) void bn_stats(
    const float* __restrict__ gq, const float* __restrict__ betaq,
    const float* __restrict__ gk, const float* __restrict__ betak,
    const float* __restrict__ gv, const float* __restrict__ betav)
{
    __shared__ float bs[8], bs2[8];
    const int p = blockIdx.x / C, c = blockIdx.x % C;
    const int lane = threadIdx.x & 31, b = threadIdx.x >> 5;

    size_t off = ((size_t)b * NT + lane) * C + c;
    float s  = g_Psum[p][off];
    float s2 = g_Psum2[p][off];
#pragma unroll
    for (int o = 16; o > 0; o >>= 1) {
        s  += __shfl_xor_sync(0xffffffffu, s, o);
        s2 += __shfl_xor_sync(0xffffffffu, s2, o);
    }
    if (lane == 0) {
        g_S[p][b * C + c] = s;
        bs[b] = s; bs2[b] = s2;
    }
    __syncthreads();
    if (threadIdx.x == 0) {
        float ts = 0.f, ts2 = 0.f;
#pragma unroll
        for (int i = 0; i < 8; i++) { ts += bs[i]; ts2 += bs2[i]; }
        const float inv_n = 1.f / (float)(B * HW);
        float mu  = ts * inv_n;
        float var = ts2 * inv_n - mu * mu;
        float inv = rsqrtf(var + BN_EPS);
        const float* gg = (p == 0) ? gq : (p == 1) ? gk : gv;
        const float* be = (p == 0) ? betaq : (p == 1) ? betak : betav;
        float a = gg[c] * inv;
        g_a[p][c] = a;
        g_d[p][c] = be[c] - mu * a;
    }
}

// ---------------------------------------------------------------------------
// K3: Gram = Vh * Kh^T, 1-term, split-K=8. grid (2,2,64), 64KB smem, 2 CTA/SM.
// ---------------------------------------------------------------------------
__global__ __launch_bounds__(256, 2) void gram_gemm()
{
    extern __shared__ char smraw[];
    uint32_t sa0 = smaddr(smraw);
    char* sm = smraw + ((1024u - (sa0 & 1023u)) & 1023u);
    const uint32_t sb = smaddr(sm);   // [buf][Vh,Kh][PLANE]

    const int tid = threadIdx.x, lane = tid & 31, wid = tid >> 5;
    const int s = blockIdx.z >> 3, b = blockIdx.z & 7;
    const int m0 = blockIdx.y * 128, n0 = blockIdx.x * 128;
    const int wm = (wid & 3) * 32, wn = (wid >> 2) * 64;

    const uint32_t* Vh = g_Yhi[2] + (size_t)b * C * (HW / 2);
    const uint32_t* Kh = g_Yhi[1] + (size_t)b * C * (HW / 2);

    auto stage = [&](int kt, int t) {
        const int kw = s * (CHUNK / 2) + kt * 32;
        const uint32_t base = sb + t * 2 * PLANE;
#pragma unroll
        for (int i = 0; i < 4; i++) {
            int idx = i * 256 + tid;
            int r = idx >> 3, u = idx & 7;
            uint32_t doff = (uint32_t)SW128(r * 128 + u * 16);
            size_t sA = (size_t)(m0 + r) * (HW / 2) + kw + u * 4;
            size_t sB = (size_t)(n0 + r) * (HW / 2) + kw + u * 4;
            cp16(base + doff,         Vh + sA);
            cp16(base + PLANE + doff, Kh + sB);
        }
        cp_commit();
    };

    stage(0, 0);
    float acc[2][8][4] = {};
#pragma unroll
    for (int kt = 0; kt < CHUNK / 64; kt++) {
        if (kt < CHUNK / 64 - 1) { stage(kt + 1, (kt + 1) & 1); cp_wait<1>(); }
        else                     { cp_wait<0>(); }
        __syncthreads();
        const uint32_t base = sb + (kt & 1) * 2 * PLANE;
        mma_chunk1(acc, base, base + PLANE, lane, wm, wn);
        __syncthreads();
    }

    float* Gp = &g_Gpart[s][(size_t)b * C * C];
    const int g = lane >> 2, tg = lane & 3;
#pragma unroll
    for (int i = 0; i < 2; i++)
#pragma unroll
        for (int j = 0; j < 8; j++) {
            int r0 = m0 + wm + i * 16 + g;
            int cc = n0 + wn + j * 8 + tg * 2;
            *(float2*)&Gp[(size_t)r0 * C + cc] = make_float2(acc[i][j][0], acc[i][j][1]);
            *(float2*)&Gp[(size_t)(r0 + 8) * C + cc] = make_float2(acc[i][j][2], acc[i][j][3]);
        }
}

// ---------------------------------------------------------------------------
// K4: reduce Gram partials + BN fold -> fp16 M2 plane + r.  grid (C,B), 256.
// ---------------------------------------------------------------------------
__global__ __launch_bounds__(256) void m_fix()
{
    __shared__ float red[256];
    const int m = blockIdx.x, b = blockIdx.y;
    const int c = threadIdx.x;
    __half* M2h = reinterpret_cast<__half*>(g_M2hi);

    const float av = g_a[2][m], dv = g_d[2][m];
    const float SV = g_S[2][b * C + m];

    const size_t rowoff = (size_t)b * C * C + (size_t)m * C + c;
    float e = 0.f;
#pragma unroll
    for (int s = 0; s < SPLIT; s++)
        e += g_Gpart[s][rowoff];

    float ak = g_a[1][c], dk = g_d[1][c];
    float SK = g_S[1][b * C + c];
    float M = av * ak * e + av * dk * SV + dv * ak * SK + 4096.f * dv * dk;
    float M2 = 0.125f * M * g_a[0][c];
    M2h[(size_t)(b * C + m) * C + c] = __float2half_rn(M2);

    red[c] = M * g_d[0][c];
    __syncthreads();
    for (int o = 128; o > 0; o >>= 1) {
        if (c < o) red[c] += red[c + o];
        __syncthreads();
    }
    if (c == 0) g_r[b * C + m] = 0.125f * red[0];
}

// ---------------------------------------------------------------------------
// K5: out = M2h * Qh + r, 1-term.  grid (32, 2, 8), 256 thr, 64KB, 2 CTA/SM.
// ---------------------------------------------------------------------------
__global__ __launch_bounds__(256, 2) void out_gemm(float* __restrict__ out)
{
    extern __shared__ char smraw[];
    uint32_t sa0 = smaddr(smraw);
    char* sm = smraw + ((1024u - (sa0 & 1023u)) & 1023u);
    const uint32_t sbA = smaddr(sm);                  // [buf][PLANE]
    const uint32_t sbB = sbA + 2 * PLANE;             // [buf][PLANE]
    char* smB = sm + 2 * PLANE;

    const int tid = threadIdx.x, lane = tid & 31, wid = tid >> 5;
    const int b = blockIdx.z;
    const int n0 = blockIdx.x * 128, m0 = blockIdx.y * 128;
    const int wm = (wid & 3) * 32, wn = (wid >> 2) * 64;

    const uint32_t* Qh = g_Yhi[0] + (size_t)b * C * (HW / 2);

    auto stageA = [&](int kt, int t) {
        const uint32_t base = sbA + t * PLANE;
#pragma unroll
        for (int i = 0; i < 4; i++) {
            int idx = i * 256 + tid;
            int r = idx >> 3, u = idx & 7;
            uint32_t doff = (uint32_t)SW128(r * 128 + u * 16);
            size_t srco = (size_t)(b * C + m0 + r) * (C / 2) + kt * 32 + u * 4;
            cp16(base + doff, g_M2hi + srco);
        }
        cp_commit();
    };

    uint32_t bu0[2][8], bu1[2][8];
    auto ldgB = [&](int kt, int t) {
        const int k0 = kt * 64;
#pragma unroll
        for (int i = 0; i < 8; i++) {
            int idx = i * 256 + tid;
            int k2 = idx >> 6, np = idx & 63;
            size_t srco = (size_t)(k0 + 2 * k2) * (HW / 2) + (n0 >> 1) + np;
            bu0[t][i] = Qh[srco]; bu1[t][i] = Qh[srco + HW / 2];
        }
    };
    auto stsB = [&](int t) {
        char* base = smB + t * PLANE;
#pragma unroll
        for (int i = 0; i < 8; i++) {
            int idx = i * 256 + tid;
            int k2 = idx >> 6, np = idx & 63;
            int offE = SW128((2 * np) * 128 + k2 * 4);
            int offO = SW128((2 * np + 1) * 128 + k2 * 4);
            *(uint32_t*)(base + offE) = __byte_perm(bu0[t][i], bu1[t][i], 0x5410);
            *(uint32_t*)(base + offO) = __byte_perm(bu0[t][i], bu1[t][i], 0x7632);
        }
    };

    ldgB(0, 0);
    stageA(0, 0);
    float acc[2][8][4] = {};
#pragma unroll
    for (int kt = 0; kt < 4; kt++) {
        stsB(kt & 1);
        if (kt < 3) {
            ldgB(kt + 1, (kt + 1) & 1);
            stageA(kt + 1, (kt + 1) & 1);
            cp_wait<1>();
        } else {
            cp_wait<0>();
        }
        __syncthreads();
        const uint32_t bA = sbA + (kt & 1) * PLANE;
        const uint32_t bB = sbB + (kt & 1) * PLANE;
        mma_chunk1(acc, bA, bB, lane, wm, wn);
        __syncthreads();
    }

    const int g = lane >> 2, tg = lane & 3;
#pragma unroll
    for (int i = 0; i < 2; i++)
#pragma unroll
        for (int j = 0; j < 8; j++) {
            int r0 = m0 + wm + i * 16 + g;
            int cc = n0 + wn + j * 8 + tg * 2;
            float rr = g_r[b * C + r0];
            *(float2*)&out[(size_t)(b * C + r0) * HW + cc] =
                make_float2(acc[i][j][0] + rr, acc[i][j][1] + rr);
            rr = g_r[b * C + r0 + 8];
            *(float2*)&out[(size_t)(b * C + r0 + 8) * HW + cc] =
                make_float2(acc[i][j][2] + rr, acc[i][j][3] + rr);
        }
}

// ---------------------------------------------------------------------------
extern "C" void kernel_launch(void* const* d_in, const int* in_sizes, int n_in,
                              void* d_out, int out_size)
{
    const float* x     = (const float*)d_in[0];
    const float* Wq    = (const float*)d_in[1];
    const float* bq    = (const float*)d_in[2];
    const float* gq    = (const float*)d_in[3];
    const float* betaq = (const float*)d_in[4];
    const float* Wk    = (const float*)d_in[5];
    const float* bk    = (const float*)d_in[6];
    const float* gk    = (const float*)d_in[7];
    const float* betak = (const float*)d_in[8];
    const float* Wv    = (const float*)d_in[9];
    const float* bv    = (const float*)d_in[10];
    const float* gv    = (const float*)d_in[11];
    const float* betav = (const float*)d_in[12];
    float* out = (float*)d_out;

    const int smFour = 4 * PLANE + 1024;   // proj, gram, out: 2 planes x 2 buf
    cudaFuncSetAttribute(proj_gemm, cudaFuncAttributeMaxDynamicSharedMemorySize, smFour);
    cudaFuncSetAttribute(gram_gemm, cudaFuncAttributeMaxDynamicSharedMemorySize, smFour);
    cudaFuncSetAttribute(out_gemm,  cudaFuncAttributeMaxDynamicSharedMemorySize, smFour);

    prep<<<24 + B * 4 * NT, 256>>>(x, Wq, Wk, Wv);
    proj_gemm<<<dim3(32, 2, 3 * B), 256, smFour>>>(bq, bk, bv);
    bn_stats<<<3 * C, 256>>>(gq, betaq, gk, betak, gv, betav);
    gram_gemm<<<dim3(2, 2, SPLIT * B), 256, smFour>>>();
    m_fix<<<dim3(C, B), 256>>>();
    out_gemm<<<dim3(32, 2, B), 256, smFour>>>(out);
}

// round 16
// speedup vs baseline: 1.0502x; 1.0502x over previous
#include <cuda_runtime.h>
#include <cuda_fp16.h>
#include <cstdint>

#define B 8
#define C 256
#define HW 4096
#define BN_EPS 1e-5f
#define SPLIT 8
#define CHUNK (HW / SPLIT)   // 512
#define NT 32
#define PLANE 16384          // 128 rows x 128 bytes
#define SW128(o) ((o) ^ (((o) >> 3) & 0x70))

// ---- device scratch ----
__device__ uint32_t g_Yhi[3][(size_t)B * C * HW / 2];   // fp16 hi plane
__device__ uint32_t g_Xsp[B][NT][4][4096];              // x hi plane, swizzled image
__device__ uint32_t g_Wsp[3][2][4][4096];               // W hi plane, swizzled image
__device__ float    g_a[3][C], g_d[3][C];
__device__ float    g_S[3][B * C];
__device__ float    g_Psum[3][(size_t)B * NT * C];
__device__ float    g_Psum2[3][(size_t)B * NT * C];
__device__ float    g_Gpart[SPLIT][(size_t)B * C * C];
__device__ uint32_t g_M2hi[(size_t)B * C * C / 2];
__device__ float    g_r[B * C];

// ---- helpers ----
__device__ __forceinline__ uint32_t smaddr(const void* p) {
    return (uint32_t)__cvta_generic_to_shared(p);
}
__device__ __forceinline__ void mma16816h(float* c, const uint32_t* a, const uint32_t* b) {
    asm volatile(
        "mma.sync.aligned.m16n8k16.row.col.f32.f16.f16.f32 "
        "{%0,%1,%2,%3}, {%4,%5,%6,%7}, {%8,%9}, {%0,%1,%2,%3};\n"
        : "+f"(c[0]), "+f"(c[1]), "+f"(c[2]), "+f"(c[3])
        : "r"(a[0]), "r"(a[1]), "r"(a[2]), "r"(a[3]), "r"(b[0]), "r"(b[1]));
}
__device__ __forceinline__ void ldfrag(uint32_t* r, uint32_t base, int row0, int kb, int lane) {
    int rl = row0 + (lane & 15);
    int cb = kb + ((lane >> 4) << 4);
    uint32_t a = base + (uint32_t)SW128(rl * 128 + cb);
    asm volatile("ldmatrix.sync.aligned.m8n8.x4.shared.b16 {%0,%1,%2,%3}, [%4];"
                 : "=r"(r[0]), "=r"(r[1]), "=r"(r[2]), "=r"(r[3]) : "r"(a));
}
// 1-term chunk: acc += Ah * Bh
__device__ __forceinline__ void mma_chunk1(
    float (*acc)[8][4], uint32_t Ah, uint32_t Bh, int lane, int wm, int wn)
{
#pragma unroll
    for (int ks = 0; ks < 4; ks++) {
        const int kb = ks * 32;
        uint32_t ah[2][4];
        ldfrag(ah[0], Ah, wm,      kb, lane);
        ldfrag(ah[1], Ah, wm + 16, kb, lane);
#pragma unroll
        for (int j = 0; j < 4; j++) {
            uint32_t bh[4];
            ldfrag(bh, Bh, wn + j * 16, kb, lane);
            uint32_t b0h[2] = {bh[0], bh[2]}, b1h[2] = {bh[1], bh[3]};
#pragma unroll
            for (int i = 0; i < 2; i++) {
                mma16816h(acc[i][2 * j],     ah[i], b0h);
                mma16816h(acc[i][2 * j + 1], ah[i], b1h);
            }
        }
    }
}
__device__ __forceinline__ void cp16(uint32_t dst, const void* src) {
    asm volatile("cp.async.cg.shared.global [%0], [%1], 16;"
                 :: "r"(dst), "l"((unsigned long long)__cvta_generic_to_global(src)) : "memory");
}
__device__ __forceinline__ void cp_commit() {
    asm volatile("cp.async.commit_group;" ::: "memory");
}
template <int N>
__device__ __forceinline__ void cp_wait() {
    asm volatile("cp.async.wait_group %0;" :: "n"(N) : "memory");
}

// ---------------------------------------------------------------------------
// K0: prep = wsplit (blocks 0..23) + xsplit (blocks 24..1047). 256 thr.
// ---------------------------------------------------------------------------
__global__ __launch_bounds__(256) void prep(
    const float* __restrict__ x,
    const float* __restrict__ Wq, const float* __restrict__ Wk,
    const float* __restrict__ Wv)
{
    const int tid = threadIdx.x;
    if (blockIdx.x < 24) {
        const int p = blockIdx.x >> 3, rem = blockIdx.x & 7;
        const int mh = rem >> 2, kt = rem & 3;
        const float* W = (p == 0) ? Wq : (p == 1) ? Wk : Wv;
        const int m0 = mh * 128, k0 = kt * 64;
        char* dh = (char*)g_Wsp[p][mh][kt];
#pragma unroll
        for (int i = 0; i < 16; i++) {
            int idx = i * 256 + tid;
            int r = idx >> 5, k2 = idx & 31;
            float2 w2 = *(const float2*)&W[(size_t)(m0 + r) * C + k0 + 2 * k2];
            __half2 hp = __floats2half2_rn(w2.x, w2.y);
            *(uint32_t*)(dh + SW128(r * 128 + k2 * 4)) = *reinterpret_cast<uint32_t*>(&hp);
        }
        return;
    }
    __shared__ float xs[64][129];
    const int id = blockIdx.x - 24;          // [b][kt][nt]
    const int nt = id & 31, kt = (id >> 5) & 3, b = id >> 7;
    const int n0 = nt * 128, c0 = kt * 64;
    const float* xb = x + (size_t)b * C * HW;

#pragma unroll
    for (int i = 0; i < 8; i++) {
        int idx = i * 256 + tid;
        int c = idx >> 5, f4 = idx & 31;
        float4 v = *(const float4*)&xb[(size_t)(c0 + c) * HW + n0 + f4 * 4];
        xs[c][f4 * 4 + 0] = v.x; xs[c][f4 * 4 + 1] = v.y;
        xs[c][f4 * 4 + 2] = v.z; xs[c][f4 * 4 + 3] = v.w;
    }
    __syncthreads();

    char* dh = (char*)g_Xsp[b][nt][kt];
#pragma unroll
    for (int i = 0; i < 16; i++) {
        int idx = i * 256 + tid;
        int n = idx >> 5, k2 = idx & 31;
        __half2 hp = __floats2half2_rn(xs[2 * k2][n], xs[2 * k2 + 1][n]);
        *(uint32_t*)(dh + SW128(n * 128 + k2 * 4)) = *reinterpret_cast<uint32_t*>(&hp);
    }
}

// ---------------------------------------------------------------------------
// K1: proj, 1-term.  grid (32, 2, 24), 256 thr, 64KB smem.
// ---------------------------------------------------------------------------
__global__ __launch_bounds__(256, 2) void proj_gemm(
    const float* __restrict__ bq, const float* __restrict__ bk,
    const float* __restrict__ bv)
{
    extern __shared__ char smraw[];
    uint32_t sa0 = smaddr(smraw);
    char* sm = smraw + ((1024u - (sa0 & 1023u)) & 1023u);
    const uint32_t sb = smaddr(sm);   // [buf][Ah,Bh][PLANE]

    const int p = blockIdx.z >> 3, b = blockIdx.z & 7;
    const float* bias = (p == 0) ? bq : (p == 1) ? bk : bv;
    const int tid = threadIdx.x, lane = tid & 31, wid = tid >> 5;
    const int nt = blockIdx.x, mh = blockIdx.y;
    const int n0 = nt * 128, m0 = mh * 128;
    const int wm = (wid & 3) * 32, wn = (wid >> 2) * 64;

    auto stage = [&](int kt, int t) {
        const uint32_t base = sb + t * 2 * PLANE;
        const uint32_t* Ah = g_Wsp[p][mh][kt];
        const uint32_t* Bh = g_Xsp[b][nt][kt];
#pragma unroll
        for (int i = 0; i < 4; i++) {
            int idx = i * 256 + tid;
            uint32_t doff = idx * 16;
            cp16(base + doff,         Ah + idx * 4);
            cp16(base + PLANE + doff, Bh + idx * 4);
        }
        cp_commit();
    };

    stage(0, 0);
    float acc[2][8][4] = {};
#pragma unroll
    for (int kt = 0; kt < 4; kt++) {
        if (kt < 3) { stage(kt + 1, (kt + 1) & 1); cp_wait<1>(); }
        else        { cp_wait<0>(); }
        __syncthreads();
        const uint32_t base = sb + (kt & 1) * 2 * PLANE;
        mma_chunk1(acc, base, base + PLANE, lane, wm, wn);
        __syncthreads();
    }

    const int g = lane >> 2, tg = lane & 3;
    float rsum[4] = {}, rsum2[4] = {};
#pragma unroll
    for (int i = 0; i < 2; i++)
#pragma unroll
        for (int j = 0; j < 8; j++) {
            int r0 = m0 + wm + i * 16 + g;
            int cc = n0 + wn + j * 8 + tg * 2;
            float bi = bias[r0];
            float y0 = acc[i][j][0] + bi, y1 = acc[i][j][1] + bi;
            rsum[i * 2]  += y0 + y1;
            rsum2[i * 2] += y0 * y0 + y1 * y1;
            __half2 hp = __floats2half2_rn(y0, y1);
            size_t off = ((size_t)(b * C + r0) * HW + cc) >> 1;
            g_Yhi[p][off] = *reinterpret_cast<uint32_t*>(&hp);
            int r1 = r0 + 8;
            bi = bias[r1];
            y0 = acc[i][j][2] + bi; y1 = acc[i][j][3] + bi;
            rsum[i * 2 + 1]  += y0 + y1;
            rsum2[i * 2 + 1] += y0 * y0 + y1 * y1;
            hp = __floats2half2_rn(y0, y1);
            off = ((size_t)(b * C + r1) * HW + cc) >> 1;
            g_Yhi[p][off] = *reinterpret_cast<uint32_t*>(&hp);
        }
#pragma unroll
    for (int q = 0; q < 4; q++) {
        rsum[q]  += __shfl_xor_sync(0xffffffffu, rsum[q], 1);
        rsum[q]  += __shfl_xor_sync(0xffffffffu, rsum[q], 2);
        rsum2[q] += __shfl_xor_sync(0xffffffffu, rsum2[q], 1);
        rsum2[q] += __shfl_xor_sync(0xffffffffu, rsum2[q], 2);
    }
    float* sbf  = (float*)sm;
    float* sbf2 = (float*)(sm + 2048);
    if (tg == 0) {
        const int half = wn >> 6;
#pragma unroll
        for (int q = 0; q < 4; q++) {
            int r = wm + (q >> 1) * 16 + (q & 1) * 8 + g;
            sbf[r * 2 + half]  = rsum[q];
            sbf2[r * 2 + half] = rsum2[q];
        }
    }
    __syncthreads();
    if (tid < 128) {
        size_t off = ((size_t)b * NT + nt) * C + m0 + tid;
        g_Psum[p][off]  = sbf[tid * 2] + sbf[tid * 2 + 1];
        g_Psum2[p][off] = sbf2[tid * 2] + sbf2[tid * 2 + 1];
    }
}

// ---------------------------------------------------------------------------
// K3: fused Gram + BN-stats.  grid (2, 2, 64 + 192), 256 thr, 64KB dyn smem.
//   z <  64 : Gram tile (s = z>>3, b = z&7, tile from x,y)
//   z >= 64 : BN-stats unit id = (z-64)*4 + y*2 + x  ->  (p, c)
// ---------------------------------------------------------------------------
__global__ __launch_bounds__(256, 2) void gram_bn(
    const float* __restrict__ gq, const float* __restrict__ betaq,
    const float* __restrict__ gk, const float* __restrict__ betak,
    const float* __restrict__ gv, const float* __restrict__ betav)
{
    const int tid = threadIdx.x;

    if (blockIdx.z >= 64) {
        // ---- BN-stats path ----
        __shared__ float bs[8], bs2[8];
        const int id = (blockIdx.z - 64) * 4 + blockIdx.y * 2 + blockIdx.x;
        const int p = id / C, c = id % C;
        const int lane = tid & 31, b = tid >> 5;

        size_t off = ((size_t)b * NT + lane) * C + c;
        float s  = g_Psum[p][off];
        float s2 = g_Psum2[p][off];
#pragma unroll
        for (int o = 16; o > 0; o >>= 1) {
            s  += __shfl_xor_sync(0xffffffffu, s, o);
            s2 += __shfl_xor_sync(0xffffffffu, s2, o);
        }
        if (lane == 0) {
            g_S[p][b * C + c] = s;
            bs[b] = s; bs2[b] = s2;
        }
        __syncthreads();
        if (tid == 0) {
            float ts = 0.f, ts2 = 0.f;
#pragma unroll
            for (int i = 0; i < 8; i++) { ts += bs[i]; ts2 += bs2[i]; }
            const float inv_n = 1.f / (float)(B * HW);
            float mu  = ts * inv_n;
            float var = ts2 * inv_n - mu * mu;
            float inv = rsqrtf(var + BN_EPS);
            const float* gg = (p == 0) ? gq : (p == 1) ? gk : gv;
            const float* be = (p == 0) ? betaq : (p == 1) ? betak : betav;
            float a = gg[c] * inv;
            g_a[p][c] = a;
            g_d[p][c] = be[c] - mu * a;
        }
        return;
    }

    // ---- Gram path ----
    extern __shared__ char smraw[];
    uint32_t sa0 = smaddr(smraw);
    char* sm = smraw + ((1024u - (sa0 & 1023u)) & 1023u);
    const uint32_t sb = smaddr(sm);   // [buf][Vh,Kh][PLANE]

    const int lane = tid & 31, wid = tid >> 5;
    const int s = blockIdx.z >> 3, b = blockIdx.z & 7;
    const int m0 = blockIdx.y * 128, n0 = blockIdx.x * 128;
    const int wm = (wid & 3) * 32, wn = (wid >> 2) * 64;

    const uint32_t* Vh = g_Yhi[2] + (size_t)b * C * (HW / 2);
    const uint32_t* Kh = g_Yhi[1] + (size_t)b * C * (HW / 2);

    auto stage = [&](int kt, int t) {
        const int kw = s * (CHUNK / 2) + kt * 32;
        const uint32_t base = sb + t * 2 * PLANE;
#pragma unroll
        for (int i = 0; i < 4; i++) {
            int idx = i * 256 + tid;
            int r = idx >> 3, u = idx & 7;
            uint32_t doff = (uint32_t)SW128(r * 128 + u * 16);
            size_t sA = (size_t)(m0 + r) * (HW / 2) + kw + u * 4;
            size_t sB = (size_t)(n0 + r) * (HW / 2) + kw + u * 4;
            cp16(base + doff,         Vh + sA);
            cp16(base + PLANE + doff, Kh + sB);
        }
        cp_commit();
    };

    stage(0, 0);
    float acc[2][8][4] = {};
#pragma unroll
    for (int kt = 0; kt < CHUNK / 64; kt++) {
        if (kt < CHUNK / 64 - 1) { stage(kt + 1, (kt + 1) & 1); cp_wait<1>(); }
        else                     { cp_wait<0>(); }
        __syncthreads();
        const uint32_t base = sb + (kt & 1) * 2 * PLANE;
        mma_chunk1(acc, base, base + PLANE, lane, wm, wn);
        __syncthreads();
    }

    float* Gp = &g_Gpart[s][(size_t)b * C * C];
    const int g = lane >> 2, tg = lane & 3;
#pragma unroll
    for (int i = 0; i < 2; i++)
#pragma unroll
        for (int j = 0; j < 8; j++) {
            int r0 = m0 + wm + i * 16 + g;
            int cc = n0 + wn + j * 8 + tg * 2;
            *(float2*)&Gp[(size_t)r0 * C + cc] = make_float2(acc[i][j][0], acc[i][j][1]);
            *(float2*)&Gp[(size_t)(r0 + 8) * C + cc] = make_float2(acc[i][j][2], acc[i][j][3]);
        }
}

// ---------------------------------------------------------------------------
// K4: reduce Gram partials + BN fold -> fp16 M2 plane + r.  grid (C,B), 256.
// ---------------------------------------------------------------------------
__global__ __launch_bounds__(256) void m_fix()
{
    __shared__ float red[256];
    const int m = blockIdx.x, b = blockIdx.y;
    const int c = threadIdx.x;
    __half* M2h = reinterpret_cast<__half*>(g_M2hi);

    const float av = g_a[2][m], dv = g_d[2][m];
    const float SV = g_S[2][b * C + m];

    const size_t rowoff = (size_t)b * C * C + (size_t)m * C + c;
    float e = 0.f;
#pragma unroll
    for (int s = 0; s < SPLIT; s++)
        e += g_Gpart[s][rowoff];

    float ak = g_a[1][c], dk = g_d[1][c];
    float SK = g_S[1][b * C + c];
    float M = av * ak * e + av * dk * SV + dv * ak * SK + 4096.f * dv * dk;
    float M2 = 0.125f * M * g_a[0][c];
    M2h[(size_t)(b * C + m) * C + c] = __float2half_rn(M2);

    red[c] = M * g_d[0][c];
    __syncthreads();
    for (int o = 128; o > 0; o >>= 1) {
        if (c < o) red[c] += red[c + o];
        __syncthreads();
    }
    if (c == 0) g_r[b * C + m] = 0.125f * red[0];
}

// ---------------------------------------------------------------------------
// K5: out = M2h * Qh + r, 1-term.  grid (32, 2, 8), 256 thr, 64KB smem.
// (no min-blocks bound: prefetch registers must not spill)
// ---------------------------------------------------------------------------
__global__ __launch_bounds__(256) void out_gemm(float* __restrict__ out)
{
    extern __shared__ char smraw[];
    uint32_t sa0 = smaddr(smraw);
    char* sm = smraw + ((1024u - (sa0 & 1023u)) & 1023u);
    const uint32_t sbA = smaddr(sm);                  // [buf][PLANE]
    const uint32_t sbB = sbA + 2 * PLANE;             // [buf][PLANE]
    char* smB = sm + 2 * PLANE;

    const int tid = threadIdx.x, lane = tid & 31, wid = tid >> 5;
    const int b = blockIdx.z;
    const int n0 = blockIdx.x * 128, m0 = blockIdx.y * 128;
    const int wm = (wid & 3) * 32, wn = (wid >> 2) * 64;

    const uint32_t* Qh = g_Yhi[0] + (size_t)b * C * (HW / 2);

    auto stageA = [&](int kt, int t) {
        const uint32_t base = sbA + t * PLANE;
#pragma unroll
        for (int i = 0; i < 4; i++) {
            int idx = i * 256 + tid;
            int r = idx >> 3, u = idx & 7;
            uint32_t doff = (uint32_t)SW128(r * 128 + u * 16);
            size_t srco = (size_t)(b * C + m0 + r) * (C / 2) + kt * 32 + u * 4;
            cp16(base + doff, g_M2hi + srco);
        }
        cp_commit();
    };

    uint32_t bu0[2][8], bu1[2][8];
    auto ldgB = [&](int kt, int t) {
        const int k0 = kt * 64;
#pragma unroll
        for (int i = 0; i < 8; i++) {
            int idx = i * 256 + tid;
            int k2 = idx >> 6, np = idx & 63;
            size_t srco = (size_t)(k0 + 2 * k2) * (HW / 2) + (n0 >> 1) + np;
            bu0[t][i] = Qh[srco]; bu1[t][i] = Qh[srco + HW / 2];
        }
    };
    auto stsB = [&](int t) {
        char* base = smB + t * PLANE;
#pragma unroll
        for (int i = 0; i < 8; i++) {
            int idx = i * 256 + tid;
            int k2 = idx >> 6, np = idx & 63;
            int offE = SW128((2 * np) * 128 + k2 * 4);
            int offO = SW128((2 * np + 1) * 128 + k2 * 4);
            *(uint32_t*)(base + offE) = __byte_perm(bu0[t][i], bu1[t][i], 0x5410);
            *(uint32_t*)(base + offO) = __byte_perm(bu0[t][i], bu1[t][i], 0x7632);
        }
    };

    ldgB(0, 0);
    stageA(0, 0);
    float acc[2][8][4] = {};
#pragma unroll
    for (int kt = 0; kt < 4; kt++) {
        stsB(kt & 1);
        if (kt < 3) {
            ldgB(kt + 1, (kt + 1) & 1);
            stageA(kt + 1, (kt + 1) & 1);
            cp_wait<1>();
        } else {
            cp_wait<0>();
        }
        __syncthreads();
        const uint32_t bA = sbA + (kt & 1) * PLANE;
        const uint32_t bB = sbB + (kt & 1) * PLANE;
        mma_chunk1(acc, bA, bB, lane, wm, wn);
        __syncthreads();
    }

    const int g = lane >> 2, tg = lane & 3;
#pragma unroll
    for (int i = 0; i < 2; i++)
#pragma unroll
        for (int j = 0; j < 8; j++) {
            int r0 = m0 + wm + i * 16 + g;
            int cc = n0 + wn + j * 8 + tg * 2;
            float rr = g_r[b * C + r0];
            *(float2*)&out[(size_t)(b * C + r0) * HW + cc] =
                make_float2(acc[i][j][0] + rr, acc[i][j][1] + rr);
            rr = g_r[b * C + r0 + 8];
            *(float2*)&out[(size_t)(b * C + r0 + 8) * HW + cc] =
                make_float2(acc[i][j][2] + rr, acc[i][j][3] + rr);
        }
}

// ---------------------------------------------------------------------------
extern "C" void kernel_launch(void* const* d_in, const int* in_sizes, int n_in,
                              void* d_out, int out_size)
{
    const float* x     = (const float*)d_in[0];
    const float* Wq    = (const float*)d_in[1];
    const float* bq    = (const float*)d_in[2];
    const float* gq    = (const float*)d_in[3];
    const float* betaq = (const float*)d_in[4];
    const float* Wk    = (const float*)d_in[5];
    const float* bk    = (const float*)d_in[6];
    const float* gk    = (const float*)d_in[7];
    const float* betak = (const float*)d_in[8];
    const float* Wv    = (const float*)d_in[9];
    const float* bv    = (const float*)d_in[10];
    const float* gv    = (const float*)d_in[11];
    const float* betav = (const float*)d_in[12];
    float* out = (float*)d_out;

    const int smFour = 4 * PLANE + 1024;   // proj, gram, out: 2 planes x 2 buf
    cudaFuncSetAttribute(proj_gemm, cudaFuncAttributeMaxDynamicSharedMemorySize, smFour);
    cudaFuncSetAttribute(gram_bn,   cudaFuncAttributeMaxDynamicSharedMemorySize, smFour);
    cudaFuncSetAttribute(out_gemm,  cudaFuncAttributeMaxDynamicSharedMemorySize, smFour);

    prep<<<24 + B * 4 * NT, 256>>>(x, Wq, Wk, Wv);
    proj_gemm<<<dim3(32, 2, 3 * B), 256, smFour>>>(bq, bk, bv);
    gram_bn<<<dim3(2, 2, 64 + 192), 256, smFour>>>(gq, betaq, gk, betak, gv, betav);
    m_fix<<<dim3(C, B), 256>>>();
    out_gemm<<<dim3(32, 2, B), 256, smFour>>>(out);
}